// round 17
// baseline (speedup 1.0000x reference)
#include <cuda_runtime.h>
#include <cuda_fp16.h>
#include <math.h>
#include <stdint.h>

#define S_LEN 2048
#define HID   2048
#define NH    32
#define NKV   8
#define HD    64

// ---------------------------------------------------------------------------
// Scratch (device globals)
// ---------------------------------------------------------------------------
__device__ float g_q[NH * S_LEN * HD];     // pre-RoPE Q fp32
__device__ float g_k[NKV * S_LEN * HD];    // pre-RoPE K fp32

__device__ __half g_X[S_LEN * HID];
__device__ __half g_Wq[HID * HID];
__device__ __half g_Wk[NKV * HD * HID];
__device__ __half g_Wv[NKV * HD * HID];
__device__ __half g_Wo[HID * HID];
__device__ __half g_Ch[S_LEN * HID];

__device__ __half g_qh[NH * S_LEN * HD];   // post-RoPE Q, pre-scaled by 0.125*log2(e)
__device__ __half g_kh[NKV * S_LEN * HD];
__device__ __half g_vh[NKV * S_LEN * HD];

// ---------------------------------------------------------------------------
// PTX helpers
// ---------------------------------------------------------------------------
__device__ __forceinline__ uint32_t s2u(const void* p) {
    uint32_t a;
    asm("{ .reg .u64 t; cvta.to.shared.u64 t, %1; cvt.u32.u64 %0, t; }" : "=r"(a) : "l"(p));
    return a;
}

__device__ __forceinline__ void ldsm4(uint32_t* r, uint32_t addr) {
    asm volatile("ldmatrix.sync.aligned.m8n8.x4.shared.b16 {%0,%1,%2,%3}, [%4];"
                 : "=r"(r[0]), "=r"(r[1]), "=r"(r[2]), "=r"(r[3]) : "r"(addr));
}

__device__ __forceinline__ void ldsm4t(uint32_t* r, uint32_t addr) {
    asm volatile("ldmatrix.sync.aligned.m8n8.x4.trans.shared.b16 {%0,%1,%2,%3}, [%4];"
                 : "=r"(r[0]), "=r"(r[1]), "=r"(r[2]), "=r"(r[3]) : "r"(addr));
}

__device__ __forceinline__ void mma16816(float* d, uint32_t a0, uint32_t a1, uint32_t a2,
                                         uint32_t a3, uint32_t b0, uint32_t b1) {
    asm volatile(
        "mma.sync.aligned.m16n8k16.row.col.f32.f16.f16.f32 "
        "{%0,%1,%2,%3}, {%4,%5,%6,%7}, {%8,%9}, {%0,%1,%2,%3};"
        : "+f"(d[0]), "+f"(d[1]), "+f"(d[2]), "+f"(d[3])
        : "r"(a0), "r"(a1), "r"(a2), "r"(a3), "r"(b0), "r"(b1));
}

__device__ __forceinline__ void cpa16(uint32_t saddr, const void* g) {
    asm volatile("cp.async.cg.shared.global [%0], [%1], 16;" :: "r"(saddr), "l"(g) : "memory");
}

__device__ __forceinline__ uint32_t packhf(float lo, float hi) {
    uint32_t r;
    asm("cvt.rn.f16x2.f32 %0, %1, %2;" : "=r"(r) : "f"(hi), "f"(lo));
    return r;
}

__device__ __forceinline__ uint32_t ex2h2(uint32_t a) {
    uint32_t r;
    asm("ex2.approx.f16x2 %0, %1;" : "=r"(r) : "r"(a));
    return r;
}

__device__ __forceinline__ float ex2f(float a) {
    float r;
    asm("ex2.approx.f32 %0, %1;" : "=f"(r) : "f"(a));
    return r;
}

// ---------------------------------------------------------------------------
// Merged fp32 -> fp16 convert for all 5 inputs, MLP=4.
// ---------------------------------------------------------------------------
#define N_X4  1048576
#define N_WQ4 1048576
#define N_WK4 262144
#define N_WV4 262144
#define N_WO4 1048576
#define N_ALL4 (N_X4 + N_WQ4 + N_WK4 + N_WV4 + N_WO4)
#define N_STRIDE (N_ALL4 / 4)

__global__ __launch_bounds__(256) void split_all(const float* __restrict__ X,
                                                 const float* __restrict__ Wq,
                                                 const float* __restrict__ Wk,
                                                 const float* __restrict__ Wv,
                                                 const float* __restrict__ Wo)
{
    const int base = blockIdx.x * 256 + threadIdx.x;

    const float* srcp[4];
    __half* hip[4];
    int offp[4];
#pragma unroll
    for (int k = 0; k < 4; ++k) {
        const int i = base + k * N_STRIDE;
        const float* src; __half* hi; int off;
        if (i < N_X4)                       { src = X;  hi = g_X;  off = i; }
        else if (i < N_X4 + N_WQ4)          { src = Wq; hi = g_Wq; off = i - N_X4; }
        else if (i < N_X4 + N_WQ4 + N_WK4)  { src = Wk; hi = g_Wk; off = i - N_X4 - N_WQ4; }
        else if (i < N_X4 + N_WQ4 + N_WK4 + N_WV4)
                                            { src = Wv; hi = g_Wv; off = i - N_X4 - N_WQ4 - N_WK4; }
        else                                { src = Wo; hi = g_Wo; off = i - N_X4 - N_WQ4 - N_WK4 - N_WV4; }
        srcp[k] = src; hip[k] = hi; offp[k] = off;
    }

    float4 v[4];
#pragma unroll
    for (int k = 0; k < 4; ++k) v[k] = ((const float4*)srcp[k])[offp[k]];

#pragma unroll
    for (int k = 0; k < 4; ++k) {
        __half h[4];
        h[0] = __float2half_rn(v[k].x);
        h[1] = __float2half_rn(v[k].y);
        h[2] = __float2half_rn(v[k].z);
        h[3] = __float2half_rn(v[k].w);
        *(uint64_t*)(hip[k] + 4 * offp[k]) = *(uint64_t*)h;
    }
}

// ---------------------------------------------------------------------------
// 128x128 single-term fp16 HMMA GEMM, K-tile 64, 2-stage cp.async (r16 proven).
// ---------------------------------------------------------------------------
#define T64_H 9216
#define T64_B (T64_H * 2)
#define GSTAGE_B (2 * T64_B)
#define GEMM_SMEM (2 * GSTAGE_B)

template <int MODE>
__global__ __launch_bounds__(256) void hgemm8_k(const float* __restrict__ bq,
                                                const float* __restrict__ bk,
                                                const float* __restrict__ bv,
                                                float* __restrict__ outp)
{
    extern __shared__ __half sm[];
    const int t = threadIdx.x, w = t >> 5, lane = t & 31;
    const int bm = blockIdx.y * 128;
    const int bn = blockIdx.x * 128;
    const int wm = (w & 3) * 32, wn = (w >> 2) * 64;

    const __half* srcA;
    const __half* srcB;
    const float* bias = nullptr;
    int outsel, bcol0;
    if (MODE == 0) {
        srcA = g_X + (size_t)bm * HID;
        if (bn < 2048)      { srcB = g_Wq; bias = bq; outsel = 0; bcol0 = bn; }
        else if (bn < 2560) { srcB = g_Wk; bias = bk; outsel = 1; bcol0 = bn - 2048; }
        else                { srcB = g_Wv; bias = bv; outsel = 2; bcol0 = bn - 2560; }
        srcB += (size_t)bcol0 * HID;
    } else {
        outsel = 3; bcol0 = bn;
        srcA = g_Ch + (size_t)bm * HID;
        srcB = g_Wo + (size_t)bcol0 * HID;
    }

    const uint32_t sb = s2u(sm);
    const uint32_t a_r = lane & 15, a_c8 = (lane >> 4) << 3;
    const uint32_t b_r = ((lane >> 4) << 3) + (lane & 7), b_c8 = ((lane >> 3) & 1) << 3;

    float acc[2][8][4];
#pragma unroll
    for (int mi = 0; mi < 2; ++mi)
#pragma unroll
        for (int ni = 0; ni < 8; ++ni)
#pragma unroll
            for (int r = 0; r < 4; ++r) acc[mi][ni][r] = 0.0f;

#define ISSUE(ktv, stg)                                                              \
    {                                                                                \
        const int _kt = (ktv);                                                       \
        const uint32_t _sb0 = sb + (uint32_t)(stg) * GSTAGE_B;                       \
        _Pragma("unroll")                                                            \
        for (int i = 0; i < 8; ++i) {                                                \
            const int idx = i * 256 + t;                                             \
            const int tile = idx >> 10;                                              \
            const int rem = idx & 1023;                                              \
            const int row = rem >> 3, ch = rem & 7;                                  \
            cpa16(_sb0 + (uint32_t)(tile * T64_H + row * 72 + ch * 8) * 2,           \
                  (tile ? srcB : srcA) + (size_t)row * HID + _kt + ch * 8);          \
        }                                                                            \
        asm volatile("cp.async.commit_group;" ::: "memory");                         \
    }

    ISSUE(0, 0);

    for (int it = 0; it < HID / 64; ++it) {
        const int cur = it & 1;
        if (it < HID / 64 - 1) {
            ISSUE((it + 1) * 64, cur ^ 1);
            asm volatile("cp.async.wait_group 1;" ::: "memory");
        } else {
            asm volatile("cp.async.wait_group 0;" ::: "memory");
        }
        __syncthreads();

        const uint32_t st = sb + (uint32_t)cur * GSTAGE_B;
#pragma unroll
        for (int ks = 0; ks < 4; ++ks) {
            const uint32_t k0 = ks * 16;
            uint32_t bf[4][4];
#pragma unroll
            for (int pi = 0; pi < 4; ++pi) {
                uint32_t off = ((wn + pi * 16 + b_r) * 72 + k0 + b_c8) * 2;
                ldsm4(bf[pi], st + T64_B + off);
            }
#pragma unroll
            for (int mi = 0; mi < 2; ++mi) {
                uint32_t ah[4];
                uint32_t off = ((wm + mi * 16 + a_r) * 72 + k0 + a_c8) * 2;
                ldsm4(ah, st + off);
#pragma unroll
                for (int pi = 0; pi < 4; ++pi) {
#pragma unroll
                    for (int half = 0; half < 2; ++half) {
                        const int ni = pi * 2 + half;
                        mma16816(acc[mi][ni], ah[0], ah[1], ah[2], ah[3],
                                 bf[pi][half * 2], bf[pi][half * 2 + 1]);
                    }
                }
            }
        }
        __syncthreads();
    }
#undef ISSUE

#pragma unroll
    for (int mi = 0; mi < 2; ++mi) {
#pragma unroll
        for (int ni = 0; ni < 8; ++ni) {
            const int lcol = wn + ni * 8 + 2 * (lane & 3);
            const int col = bcol0 + lcol;
            float b0 = 0.f, b1 = 0.f;
            if (MODE == 0) { b0 = bias[col]; b1 = bias[col + 1]; }
#pragma unroll
            for (int rr = 0; rr < 2; ++rr) {
                const int row = bm + wm + mi * 16 + (lane >> 2) + rr * 8;
                float vx = acc[mi][ni][rr * 2 + 0] + b0;
                float vy = acc[mi][ni][rr * 2 + 1] + b1;
                if (outsel == 0 || outsel == 1) {
                    const int head = col >> 6, d = col & 63;
                    float* dst = (outsel == 0) ? g_q : g_k;
                    float2 v2 = {vx, vy};
                    *(float2*)(dst + ((size_t)head * S_LEN + row) * HD + d) = v2;
                } else if (outsel == 2) {
                    const int head = col >> 6, d = col & 63;
                    *(uint32_t*)(g_vh + ((size_t)head * S_LEN + row) * HD + d) = packhf(vx, vy);
                } else {
                    float2 v2 = {vx, vy};
                    *(float2*)(outp + (size_t)row * HID + col) = v2;
                }
            }
        }
    }
}

// ---------------------------------------------------------------------------
// RoPE: Q pre-scaled by 0.125*log2(e) (log2-domain logits); K plain.
// ---------------------------------------------------------------------------
#define ROPE_Q_N (NH * S_LEN * 16)
#define ROPE_K_N (NKV * S_LEN * 16)
#define QSCALE 0.18033688f   // 0.125 * log2(e)

__global__ __launch_bounds__(256) void rope_all()
{
    int idx = blockIdx.x * 256 + threadIdx.x;
    const bool isQ = (idx < ROPE_Q_N);
    if (!isQ) idx -= ROPE_Q_N;

    const int j2 = (idx & 15) * 2;
    const int s = (idx >> 4) & (S_LEN - 1);
    const int h = idx >> 15;
    const size_t base = ((size_t)h * S_LEN + s) * HD;

    const float* src = (isQ ? g_q : g_k) + base;
    const float qscale = isQ ? QSCALE : 1.0f;
    float y1[2], y2[2];
#pragma unroll
    for (int e = 0; e < 2; ++e) {
        const int j = j2 + e;
        const float inv_freq = __powf(10000.0f, -((float)(2 * j)) / 64.0f);
        float sn, cs;
        sincosf((float)s * inv_freq, &sn, &cs);
        const float x1 = src[j], x2 = src[j + 32];
        y1[e] = (x1 * cs - x2 * sn) * qscale;
        y2[e] = (x2 * cs + x1 * sn) * qscale;
    }
    __half* dst = (isQ ? g_qh : g_kh) + base;
    *(uint32_t*)(dst + j2) = packhf(y1[0], y1[1]);
    *(uint32_t*)(dst + j2 + 32) = packhf(y2[0], y2[1]);
}

// ---------------------------------------------------------------------------
// HMMA flash attention: log2-domain softmax with ex2.approx.f16x2.
// Single-term fp16 Q,K,P,V. Split K/V cp.async pipeline. 36864 B smem.
// ---------------------------------------------------------------------------
#define TILE_B 9216
#define AT_Q  0
#define AT_K0 9216
#define AT_K1 18432
#define AT_V  27648
#define ATTN_SMEM 36864

__global__ __launch_bounds__(128, 3) void attn_k()
{
    extern __shared__ __half smb[];
    const uint32_t sb = s2u(smb);
    const int h = blockIdx.y;
    const int zz = blockIdx.x;
    const int qb = (zz & 1) ? (31 - (zz >> 1)) : (zz >> 1);
    const int kvh = h >> 2;

    const int t = threadIdx.x, w = t >> 5, lane = t & 31;
    const size_t kvbase = (size_t)kvh * S_LEN * HD;

#define CPT(dstoff, src)                                                            \
    {                                                                               \
        _Pragma("unroll")                                                           \
        for (int ii = 0; ii < 4; ++ii) {                                            \
            const int rem = ii * 128 + t;                                           \
            const int row = rem >> 3, ch = rem & 7;                                 \
            cpa16(sb + (dstoff) + (row * 72 + ch * 8) * 2,                          \
                  (src) + row * 64 + ch * 8);                                       \
        }                                                                           \
        asm volatile("cp.async.commit_group;" ::: "memory");                        \
    }

    CPT(AT_K0, g_kh + kvbase);

    {
        const __half* qh = g_qh + ((size_t)h * S_LEN + (size_t)qb * 64) * HD;
#pragma unroll
        for (int ii = 0; ii < 4; ++ii) {
            const int i = ii * 128 + t;
            const int row = i >> 3, ch = i & 7;
            *(uint4*)((char*)smb + AT_Q + (row * 72 + ch * 8) * 2) =
                *(const uint4*)(qh + row * 64 + ch * 8);
        }
    }
    __syncthreads();

    const uint32_t a_r = lane & 15, a_c8 = (lane >> 4) << 3;
    const uint32_t b_r = ((lane >> 4) << 3) + (lane & 7), b_c8 = ((lane >> 3) & 1) << 3;
    uint32_t qf[4][4];
#pragma unroll
    for (int ks = 0; ks < 4; ++ks) {
        uint32_t off = ((w * 16 + a_r) * 72 + ks * 16 + a_c8) * 2;
        ldsm4(qf[ks], sb + AT_Q + off);
    }

    float oacc[8][4];
#pragma unroll
    for (int nt = 0; nt < 8; ++nt)
#pragma unroll
        for (int e = 0; e < 4; ++e) oacc[nt][e] = 0.0f;
    float m_i[2] = {-1e30f, -1e30f}, l_i[2] = {0.0f, 0.0f};

    const int grow0 = qb * 64 + w * 16 + (lane >> 2);

    for (int kb = 0; kb <= qb; ++kb) {
        const uint32_t KHB = (kb & 1) ? AT_K1 : AT_K0;
        __syncthreads();
        CPT(AT_V, g_vh + kvbase + (size_t)kb * 64 * HD);
        asm volatile("cp.async.wait_group 1;" ::: "memory");
        __syncthreads();

        // ---- S = Q K^T (log2-domain logits; Q pre-scaled) ----
        float sacc[8][4];
#pragma unroll
        for (int nt = 0; nt < 8; ++nt)
#pragma unroll
            for (int e = 0; e < 4; ++e) sacc[nt][e] = 0.0f;

#pragma unroll
        for (int ks = 0; ks < 4; ++ks) {
#pragma unroll
            for (int np = 0; np < 4; ++np) {
                uint32_t BH[4];
                uint32_t off = ((np * 16 + b_r) * 72 + ks * 16 + b_c8) * 2;
                ldsm4(BH, sb + KHB + off);
#pragma unroll
                for (int half = 0; half < 2; ++half) {
                    const int nt = np * 2 + half;
                    mma16816(sacc[nt], qf[ks][0], qf[ks][1], qf[ks][2], qf[ks][3],
                             BH[half * 2], BH[half * 2 + 1]);
                }
            }
        }

        if (kb < qb) {
            const uint32_t nstage = (kb & 1) ? AT_K0 : AT_K1;
            CPT(nstage, g_kh + kvbase + (size_t)(kb + 1) * 64 * HD);
        }

        // ---- online softmax (log2 domain, fp16x2 exp) ----
        const bool diag = (kb == qb);
        float mt[2] = {-1e30f, -1e30f};
        if (diag) {
#pragma unroll
            for (int nt = 0; nt < 8; ++nt)
#pragma unroll
                for (int e = 0; e < 4; ++e) {
                    const int col = kb * 64 + nt * 8 + 2 * (lane & 3) + (e & 1);
                    const int row = grow0 + (e >> 1) * 8;
                    if (col > row) sacc[nt][e] = -1e30f;
                    mt[e >> 1] = fmaxf(mt[e >> 1], sacc[nt][e]);
                }
        } else {
#pragma unroll
            for (int nt = 0; nt < 8; ++nt)
#pragma unroll
                for (int e = 0; e < 4; ++e)
                    mt[e >> 1] = fmaxf(mt[e >> 1], sacc[nt][e]);
        }
#pragma unroll
        for (int o = 1; o < 4; o <<= 1) {
            mt[0] = fmaxf(mt[0], __shfl_xor_sync(0xffffffffu, mt[0], o));
            mt[1] = fmaxf(mt[1], __shfl_xor_sync(0xffffffffu, mt[1], o));
        }
        float corr[2], rs[2] = {0.0f, 0.0f};
#pragma unroll
        for (int rr = 0; rr < 2; ++rr) {
            const float mn = fmaxf(m_i[rr], mt[rr]);
            corr[rr] = ex2f(m_i[rr] - mn);
            m_i[rr] = mn;
        }

        // p = exp2(sacc - m) computed pairwise in fp16; result IS the PV operand
        uint32_t pp[8][2];
#pragma unroll
        for (int nt = 0; nt < 8; ++nt) {
            pp[nt][0] = ex2h2(packhf(sacc[nt][0] - m_i[0], sacc[nt][1] - m_i[0]));
            pp[nt][1] = ex2h2(packhf(sacc[nt][2] - m_i[1], sacc[nt][3] - m_i[1]));
            float2 f0 = __half22float2(*(__half2*)&pp[nt][0]);
            float2 f1 = __half22float2(*(__half2*)&pp[nt][1]);
            rs[0] += f0.x + f0.y;
            rs[1] += f1.x + f1.y;
        }
#pragma unroll
        for (int o = 1; o < 4; o <<= 1) {
            rs[0] += __shfl_xor_sync(0xffffffffu, rs[0], o);
            rs[1] += __shfl_xor_sync(0xffffffffu, rs[1], o);
        }
#pragma unroll
        for (int rr = 0; rr < 2; ++rr) l_i[rr] = l_i[rr] * corr[rr] + rs[rr];
#pragma unroll
        for (int nt = 0; nt < 8; ++nt)
#pragma unroll
            for (int e = 0; e < 4; ++e) oacc[nt][e] *= corr[e >> 1];

        // ---- wait V, then PV (P already packed fp16) ----
        if (kb < qb) asm volatile("cp.async.wait_group 1;" ::: "memory");
        else         asm volatile("cp.async.wait_group 0;" ::: "memory");
        __syncthreads();

#pragma unroll
        for (int ks = 0; ks < 4; ++ks) {
            const int L = 2 * ks, R = 2 * ks + 1;
#pragma unroll
            for (int dp = 0; dp < 4; ++dp) {
                uint32_t VH4[4];
                uint32_t voff = ((ks * 16 + (lane & 7) + ((lane >> 3) & 1) * 8) * 72
                                 + dp * 16 + ((lane >> 4) << 3)) * 2;
                ldsm4t(VH4, sb + AT_V + voff);
#pragma unroll
                for (int half = 0; half < 2; ++half) {
                    const int nt = dp * 2 + half;
                    mma16816(oacc[nt], pp[L][0], pp[L][1], pp[R][0], pp[R][1],
                             VH4[half * 2], VH4[half * 2 + 1]);
                }
            }
        }
    }
#undef CPT

    const float inv0 = 1.0f / l_i[0], inv1 = 1.0f / l_i[1];
#pragma unroll
    for (int nt = 0; nt < 8; ++nt) {
#pragma unroll
        for (int rr = 0; rr < 2; ++rr) {
            const float inv = rr ? inv1 : inv0;
            const float v0 = oacc[nt][rr * 2 + 0] * inv;
            const float v1 = oacc[nt][rr * 2 + 1] * inv;
            const int srow = qb * 64 + w * 16 + (lane >> 2) + rr * 8;
            const int col = h * 64 + nt * 8 + 2 * (lane & 3);
            *(uint32_t*)(g_Ch + (size_t)srow * HID + col) = packhf(v0, v1);
        }
    }
}

// ---------------------------------------------------------------------------
// Launcher
// ---------------------------------------------------------------------------
extern "C" void kernel_launch(void* const* d_in, const int* in_sizes, int n_in,
                              void* d_out, int out_size)
{
    const float* X  = (const float*)d_in[0];
    const float* Wq = (const float*)d_in[2];
    const float* bq = (const float*)d_in[3];
    const float* Wk = (const float*)d_in[4];
    const float* bk = (const float*)d_in[5];
    const float* Wv = (const float*)d_in[6];
    const float* bv = (const float*)d_in[7];
    const float* Wo = (const float*)d_in[8];
    float* out = (float*)d_out;

    split_all<<<N_STRIDE / 256, 256>>>(X, Wq, Wk, Wv, Wo);

    cudaFuncSetAttribute(hgemm8_k<0>, cudaFuncAttributeMaxDynamicSharedMemorySize, GEMM_SMEM);
    cudaFuncSetAttribute(hgemm8_k<1>, cudaFuncAttributeMaxDynamicSharedMemorySize, GEMM_SMEM);

    hgemm8_k<0><<<dim3(24, S_LEN / 128), 256, GEMM_SMEM>>>(bq, bk, bv, nullptr);

    rope_all<<<(ROPE_Q_N + ROPE_K_N) / 256, 256>>>();

    cudaFuncSetAttribute(attn_k, cudaFuncAttributeMaxDynamicSharedMemorySize, ATTN_SMEM);
    attn_k<<<dim3(32, NH), 128, ATTN_SMEM>>>();

    hgemm8_k<1><<<dim3(16, S_LEN / 128), 256, GEMM_SMEM>>>(nullptr, nullptr, nullptr, out);
}